// round 3
// baseline (speedup 1.0000x reference)
#include <cuda_runtime.h>

#define NB 32
#define NT 196
#define PD 768
#define DM 512
#define NC 1000
#define MTOT (NB*NT)

__device__ float g_X [(size_t)MTOT*PD];
__device__ float g_Q [(size_t)MTOT*DM];
__device__ float g_V [(size_t)MTOT*DM];
__device__ float g_M [(size_t)NB*NT*NT];
__device__ float g_Xa[(size_t)NB*NT*NT];
__device__ float g_Xb[(size_t)NB*NT*NT];
__device__ float g_T [(size_t)NB*NT*NT];
__device__ float g_P [(size_t)NB*NT*NT];
__device__ float g_Cf[(size_t)NB*NT*NT];
__device__ float g_O [(size_t)MTOT*DM];
__device__ float g_pool[NB*DM];

__device__ __forceinline__ float clipf(float x){ return fminf(fmaxf(x, 0.f), 1.f); }

// ---------------- patchify + LN(768) + pos ----------------
__global__ void k_patchify(const float* __restrict__ img, const float* __restrict__ g,
                           const float* __restrict__ bb, const float* __restrict__ pos){
    int bn = blockIdx.x, b = bn / NT, n = bn % NT;
    int hh = n / 14, ww = n % 14;
    int tid = threadIdx.x, ph = tid >> 4, pw = tid & 15;
    const float* ib = img + (size_t)b*3*224*224 + (size_t)(hh*16+ph)*224 + (ww*16+pw);
    float v0 = ib[0], v1 = ib[224*224], v2 = ib[2*224*224];
    __shared__ float red[256]; __shared__ float smu, srs;
    red[tid] = v0+v1+v2; __syncthreads();
    for (int o=128;o;o>>=1){ if (tid<o) red[tid]+=red[tid+o]; __syncthreads(); }
    if (!tid) smu = red[0]/768.f;
    __syncthreads();
    float mu = smu, d0=v0-mu, d1=v1-mu, d2=v2-mu;
    red[tid] = d0*d0+d1*d1+d2*d2; __syncthreads();
    for (int o=128;o;o>>=1){ if (tid<o) red[tid]+=red[tid+o]; __syncthreads(); }
    if (!tid) srs = rsqrtf(red[0]/768.f + 1e-5f);
    __syncthreads();
    float rs = srs;
    float* xo = g_X + (size_t)bn*PD;
    const float* pp = pos + (size_t)n*PD;
    int q = tid;     xo[q] = d0*rs*g[q] + bb[q] + pp[q];
    q = 256+tid;     xo[q] = d1*rs*g[q] + bb[q] + pp[q];
    q = 512+tid;     xo[q] = d2*rs*g[q] + bb[q] + pp[q];
}

// ---------------- exact-fit GEMM + bias (projections) ----------------
__global__ void k_gemm_bias(const float* __restrict__ A, const float* __restrict__ B,
                            const float* __restrict__ bias, float* __restrict__ C,
                            int M, int N, int K){
    __shared__ float As[16][64], Bs[16][64];
    int tid = threadIdx.x;
    int m0 = blockIdx.y<<6, n0 = blockIdx.x<<6;
    int aRow = tid>>2, aK = (tid&3)<<2;
    int bRow = tid>>4, bN = (tid&15)<<2;
    int ty = tid>>4, tx = tid&15;
    const float* Ap = A + (size_t)(m0+aRow)*K + aK;
    const float* Bp = B + (size_t)bRow*N + n0 + bN;
    float acc[4][4] = {};
    for (int k0=0;k0<K;k0+=16){
        float4 a = *(const float4*)(Ap + k0);
        float4 bv = *(const float4*)(Bp + (size_t)k0*N);
        As[aK+0][aRow]=a.x; As[aK+1][aRow]=a.y; As[aK+2][aRow]=a.z; As[aK+3][aRow]=a.w;
        *(float4*)&Bs[bRow][bN] = bv;
        __syncthreads();
#pragma unroll
        for (int kk=0;kk<16;kk++){
            float4 av = *(const float4*)&As[kk][ty<<2];
            float4 bw = *(const float4*)&Bs[kk][tx<<2];
#pragma unroll
            for (int r=0;r<4;r++){
                float am = r==0?av.x:r==1?av.y:r==2?av.z:av.w;
                acc[r][0]=fmaf(am,bw.x,acc[r][0]); acc[r][1]=fmaf(am,bw.y,acc[r][1]);
                acc[r][2]=fmaf(am,bw.z,acc[r][2]); acc[r][3]=fmaf(am,bw.w,acc[r][3]);
            }
        }
        __syncthreads();
    }
    float4 bi = *(const float4*)(bias + n0 + (tx<<2));
#pragma unroll
    for (int r=0;r<4;r++){
        float4 o = make_float4(acc[r][0]+bi.x, acc[r][1]+bi.y, acc[r][2]+bi.z, acc[r][3]+bi.w);
        *(float4*)(C + (size_t)(m0+(ty<<2)+r)*N + n0 + (tx<<2)) = o;
    }
}

// ---------------- in-place rowwise LN(512), then *scale ----------------
__global__ void k_ln512(float* __restrict__ y0, const float* __restrict__ g,
                        const float* __restrict__ bb, float scale){
    float* y = y0 + (size_t)blockIdx.x*DM;
    int tid = threadIdx.x;
    float v0 = y[tid], v1 = y[tid+256];
    __shared__ float red[256]; __shared__ float smu, srs;
    red[tid] = v0+v1; __syncthreads();
    for (int o=128;o;o>>=1){ if (tid<o) red[tid]+=red[tid+o]; __syncthreads(); }
    if (!tid) smu = red[0]/512.f;
    __syncthreads();
    float mu = smu, d0=v0-mu, d1=v1-mu;
    red[tid] = d0*d0+d1*d1; __syncthreads();
    for (int o=128;o;o>>=1){ if (tid<o) red[tid]+=red[tid+o]; __syncthreads(); }
    if (!tid) srs = rsqrtf(red[0]/512.f + 1e-5f);
    __syncthreads();
    float rs = srs;
    y[tid]     = (d0*rs*g[tid]     + bb[tid])     * scale;
    y[tid+256] = (d1*rs*g[tid+256] + bb[tid+256]) * scale;
}

// ---------------- batched GEMM: C = alpha*A@op(B) + c0 + diag*I ----------------
__global__ void k_bgemm(const float* __restrict__ A0, const float* __restrict__ B0,
                        float* __restrict__ C0, int M, int N, int K, int transB,
                        float alpha, float c0, float diag){
    const float* A = A0 + (size_t)blockIdx.z*M*K;
    const float* B = B0 + (size_t)blockIdx.z*(size_t)N*K;
    float* C = C0 + (size_t)blockIdx.z*M*N;
    __shared__ float As[16][64], Bs[16][64];
    int tid = threadIdx.x;
    int m0 = blockIdx.y<<6, n0 = blockIdx.x<<6;
    int ty = tid>>4, tx = tid&15;
    float acc[4][4] = {};
    for (int k0=0;k0<K;k0+=16){
        {   int aRow = tid>>2, aK = (tid&3)<<2;
            int gm = m0+aRow, gk = k0+aK;
            float a0=0,a1=0,a2=0,a3=0;
            if (gm < M){
                if (gk+3 < K){ float4 t = *(const float4*)(A+(size_t)gm*K+gk); a0=t.x;a1=t.y;a2=t.z;a3=t.w; }
                else { if(gk<K)a0=A[(size_t)gm*K+gk]; if(gk+1<K)a1=A[(size_t)gm*K+gk+1];
                       if(gk+2<K)a2=A[(size_t)gm*K+gk+2]; if(gk+3<K)a3=A[(size_t)gm*K+gk+3]; }
            }
            As[aK+0][aRow]=a0; As[aK+1][aRow]=a1; As[aK+2][aRow]=a2; As[aK+3][aRow]=a3;
        }
        if (transB){
            int bRow = tid>>2, bK = (tid&3)<<2;
            int gn = n0+bRow, gk = k0+bK;
            float b0=0,b1=0,b2=0,b3=0;
            if (gn < N){
                if (gk+3 < K){ float4 t = *(const float4*)(B+(size_t)gn*K+gk); b0=t.x;b1=t.y;b2=t.z;b3=t.w; }
                else { if(gk<K)b0=B[(size_t)gn*K+gk]; if(gk+1<K)b1=B[(size_t)gn*K+gk+1];
                       if(gk+2<K)b2=B[(size_t)gn*K+gk+2]; if(gk+3<K)b3=B[(size_t)gn*K+gk+3]; }
            }
            Bs[bK+0][bRow]=b0; Bs[bK+1][bRow]=b1; Bs[bK+2][bRow]=b2; Bs[bK+3][bRow]=b3;
        } else {
            int bRow = tid>>4, bN = (tid&15)<<2;
            int gk = k0+bRow, gn = n0+bN;
            float4 bv = make_float4(0.f,0.f,0.f,0.f);
            if (gk < K){
                if (gn+3 < N) bv = *(const float4*)(B+(size_t)gk*N+gn);
                else { if(gn<N)bv.x=B[(size_t)gk*N+gn]; if(gn+1<N)bv.y=B[(size_t)gk*N+gn+1];
                       if(gn+2<N)bv.z=B[(size_t)gk*N+gn+2]; if(gn+3<N)bv.w=B[(size_t)gk*N+gn+3]; }
            }
            *(float4*)&Bs[bRow][bN] = bv;
        }
        __syncthreads();
#pragma unroll
        for (int kk=0;kk<16;kk++){
            float4 av = *(const float4*)&As[kk][ty<<2];
            float4 bw = *(const float4*)&Bs[kk][tx<<2];
#pragma unroll
            for (int r=0;r<4;r++){
                float am = r==0?av.x:r==1?av.y:r==2?av.z:av.w;
                acc[r][0]=fmaf(am,bw.x,acc[r][0]); acc[r][1]=fmaf(am,bw.y,acc[r][1]);
                acc[r][2]=fmaf(am,bw.z,acc[r][2]); acc[r][3]=fmaf(am,bw.w,acc[r][3]);
            }
        }
        __syncthreads();
    }
#pragma unroll
    for (int r=0;r<4;r++){
        int gm = m0+(ty<<2)+r;
        if (gm >= M) continue;
#pragma unroll
        for (int j=0;j<4;j++){
            int gn = n0+(tx<<2)+j;
            if (gn >= N) continue;
            C[(size_t)gm*N+gn] = alpha*acc[r][j] + c0 + ((gm==gn)?diag:0.f);
        }
    }
}

// ---------------- fused ADMM: 50 iterations per CTA, no global sync ----------------
// grid (4 token-blocks, 32 batches), 343 threads: ii=tid/7 owns i0=ii*4..+3 (m-dim),
// nn=tid%7 owns tokens nn*7..+6. smem: Minv[196][196] + rhs[49][200].
__global__ void k_admm(const float* __restrict__ Minv, const float* __restrict__ P,
                       float* __restrict__ Cf){
    extern __shared__ float sm[];
    float* sM = sm;              // 196*196
    float* sR = sm + 196*196;    // 49*200
    int b = blockIdx.y, tb = blockIdx.x;
    int tid = threadIdx.x;
    int ii = tid/7, nn = tid%7, i0 = ii<<2;
    const float* Mb = Minv + (size_t)b*NT*NT;
    for (int idx = tid; idx < NT*NT; idx += 343) sM[idx] = Mb[idx];
    float p[7][4], s[7][4];
    const float* Pb = P + ((size_t)b*NT + tb*49)*NT;
#pragma unroll
    for (int t=0;t<7;t++){
        float4 v = *(const float4*)(Pb + (size_t)(nn*7+t)*NT + i0);
        p[t][0]=v.x; p[t][1]=v.y; p[t][2]=v.z; p[t][3]=v.w;
    }
    __syncthreads();
    for (int it=0; it<50; it++){
#pragma unroll
        for (int t=0;t<7;t++){
            float4 rv;
            if (it==0){ rv.x=-p[t][0]; rv.y=-p[t][1]; rv.z=-p[t][2]; rv.w=-p[t][3]; }
            else {
                rv.x = 2.f*clipf(s[t][0]) - s[t][0] - p[t][0];
                rv.y = 2.f*clipf(s[t][1]) - s[t][1] - p[t][1];
                rv.z = 2.f*clipf(s[t][2]) - s[t][2] - p[t][2];
                rv.w = 2.f*clipf(s[t][3]) - s[t][3] - p[t][3];
            }
            *(float4*)(sR + (nn*7+t)*200 + i0) = rv;
        }
        __syncthreads();
        float acc[7][4] = {};
        const float* mr0 = sM + (size_t)i0*NT;
        for (int j=0;j<NT;j+=4){
            float4 m0 = *(const float4*)(mr0 + j);
            float4 m1 = *(const float4*)(mr0 + NT + j);
            float4 m2 = *(const float4*)(mr0 + 2*NT + j);
            float4 m3 = *(const float4*)(mr0 + 3*NT + j);
#pragma unroll
            for (int t=0;t<7;t++){
                float4 r = *(const float4*)(sR + (nn*7+t)*200 + j);
                acc[t][0]=fmaf(m0.x,r.x,fmaf(m0.y,r.y,fmaf(m0.z,r.z,fmaf(m0.w,r.w,acc[t][0]))));
                acc[t][1]=fmaf(m1.x,r.x,fmaf(m1.y,r.y,fmaf(m1.z,r.z,fmaf(m1.w,r.w,acc[t][1]))));
                acc[t][2]=fmaf(m2.x,r.x,fmaf(m2.y,r.y,fmaf(m2.z,r.z,fmaf(m2.w,r.w,acc[t][2]))));
                acc[t][3]=fmaf(m3.x,r.x,fmaf(m3.y,r.y,fmaf(m3.z,r.z,fmaf(m3.w,r.w,acc[t][3]))));
            }
        }
#pragma unroll
        for (int t=0;t<7;t++)
#pragma unroll
            for (int r=0;r<4;r++)
                s[t][r] = (it==0) ? acc[t][r] : acc[t][r] + s[t][r] - clipf(s[t][r]);
        __syncthreads();
    }
    // final z = clip(s); normalize rows by sum(|z|)=sum(z); write coeffs
#pragma unroll
    for (int t=0;t<7;t++){
        float4 zv = make_float4(clipf(s[t][0]),clipf(s[t][1]),clipf(s[t][2]),clipf(s[t][3]));
        *(float4*)(sR + (nn*7+t)*200 + i0) = zv;
    }
    __syncthreads();
    if (tid < 49){
        float sum = 0.f;
        for (int j=0;j<NT;j++) sum += sR[tid*200+j];
        sM[tid] = 1.f/(sum + 1e-10f);
    }
    __syncthreads();
    float* Cb = Cf + ((size_t)b*NT + tb*49)*NT;
#pragma unroll
    for (int t=0;t<7;t++){
        int ln = nn*7+t;
        float inv = sM[ln];
        float4 zv = *(const float4*)(sR + ln*200 + i0);
        zv.x*=inv; zv.y*=inv; zv.z*=inv; zv.w*=inv;
        *(float4*)(Cb + (size_t)ln*NT + i0) = zv;
    }
}

// ---------------- pool: mean over tokens ----------------
__global__ void k_pool(const float* __restrict__ O, float* __restrict__ pooled){
    int b = blockIdx.x, tid = threadIdx.x;
    const float* Ob = O + (size_t)b*NT*DM;
    float s0=0.f, s1=0.f;
    for (int n=0;n<NT;n++){ s0 += Ob[(size_t)n*DM+tid]; s1 += Ob[(size_t)n*DM+256+tid]; }
    pooled[b*DM+tid] = s0/(float)NT;
    pooled[b*DM+256+tid] = s1/(float)NT;
}

// ---------------- head: LN + GEMM(512x1000) + softmax ----------------
__global__ void k_head(const float* __restrict__ pooled, const float* __restrict__ g,
                       const float* __restrict__ bb, const float* __restrict__ W,
                       const float* __restrict__ wb, float* __restrict__ out){
    int b = blockIdx.x, tid = threadIdx.x;
    __shared__ float xs[512]; __shared__ float red[256]; __shared__ float smu, srs, sred;
    float v0 = pooled[b*DM+tid], v1 = pooled[b*DM+256+tid];
    red[tid] = v0+v1; __syncthreads();
    for (int o=128;o;o>>=1){ if (tid<o) red[tid]+=red[tid+o]; __syncthreads(); }
    if (!tid) smu = red[0]/512.f;
    __syncthreads();
    float mu = smu, d0=v0-mu, d1=v1-mu;
    red[tid] = d0*d0+d1*d1; __syncthreads();
    for (int o=128;o;o>>=1){ if (tid<o) red[tid]+=red[tid+o]; __syncthreads(); }
    if (!tid) srs = rsqrtf(red[0]/512.f + 1e-5f);
    __syncthreads();
    float rs = srs;
    xs[tid] = d0*rs*g[tid]+bb[tid];
    xs[tid+256] = d1*rs*g[tid+256]+bb[tid+256];
    __syncthreads();
    float lg[4];
#pragma unroll
    for (int c4=0;c4<4;c4++){
        int c = c4*256 + tid;
        float acc = 0.f;
        if (c < NC){
            for (int k=0;k<512;k++) acc = fmaf(xs[k], W[(size_t)k*NC+c], acc);
            acc += wb[c];
        } else acc = -1e30f;
        lg[c4] = acc;
    }
    float mx = fmaxf(fmaxf(lg[0],lg[1]),fmaxf(lg[2],lg[3]));
    red[tid] = mx; __syncthreads();
    for (int o=128;o;o>>=1){ if (tid<o) red[tid]=fmaxf(red[tid],red[tid+o]); __syncthreads(); }
    if (!tid) sred = red[0];
    __syncthreads();
    mx = sred;
    float es = 0.f;
#pragma unroll
    for (int c4=0;c4<4;c4++){ lg[c4] = __expf(lg[c4]-mx); if (c4*256+tid < NC) es += lg[c4]; }
    red[tid] = es; __syncthreads();
    for (int o=128;o;o>>=1){ if (tid<o) red[tid]+=red[tid+o]; __syncthreads(); }
    if (!tid) sred = red[0];
    __syncthreads();
    float inv = 1.f/sred;
#pragma unroll
    for (int c4=0;c4<4;c4++){ int c = c4*256+tid; if (c < NC) out[(size_t)b*NC+c] = lg[c4]*inv; }
}

extern "C" void kernel_launch(void* const* d_in, const int* in_sizes, int n_in,
                              void* d_out, int out_size){
    const float* img   = (const float*)d_in[0];
    const float* lpg   = (const float*)d_in[1];
    const float* lpb   = (const float*)d_in[2];
    const float* wq_w  = (const float*)d_in[3];
    const float* wq_b  = (const float*)d_in[4];
    const float* lnq_g = (const float*)d_in[5];
    const float* lnq_b = (const float*)d_in[6];
    const float* wv_w  = (const float*)d_in[7];
    const float* wv_b  = (const float*)d_in[8];
    const float* lnv_g = (const float*)d_in[9];
    const float* lnv_b = (const float*)d_in[10];
    const float* pos   = (const float*)d_in[11];
    const float* mlg   = (const float*)d_in[12];
    const float* mlb   = (const float*)d_in[13];
    const float* mlw   = (const float*)d_in[14];
    const float* mlwb  = (const float*)d_in[15];
    float* out = (float*)d_out;

    float *pX,*pQ,*pV,*pM,*pXa,*pXb,*pT,*pP,*pCf,*pO,*pPool;
    cudaGetSymbolAddress((void**)&pX, g_X);
    cudaGetSymbolAddress((void**)&pQ, g_Q);
    cudaGetSymbolAddress((void**)&pV, g_V);
    cudaGetSymbolAddress((void**)&pM, g_M);
    cudaGetSymbolAddress((void**)&pXa, g_Xa);
    cudaGetSymbolAddress((void**)&pXb, g_Xb);
    cudaGetSymbolAddress((void**)&pT, g_T);
    cudaGetSymbolAddress((void**)&pP, g_P);
    cudaGetSymbolAddress((void**)&pCf, g_Cf);
    cudaGetSymbolAddress((void**)&pO, g_O);
    cudaGetSymbolAddress((void**)&pPool, g_pool);

    const int admm_smem = (NT*NT + 49*200)*4;
    static int s_attr_done = 0;
    if (!s_attr_done){
        cudaFuncSetAttribute(k_admm, cudaFuncAttributeMaxDynamicSharedMemorySize, admm_smem);
        s_attr_done = 1;
    }

    // 1. patchify + LN + pos
    k_patchify<<<MTOT, 256>>>(img, lpg, lpb, pos);
    // 2-5. projections + LN (V scaled by 1/196)
    k_gemm_bias<<<dim3(DM/64, MTOT/64), 256>>>(pX, wq_w, wq_b, pQ, MTOT, DM, PD);
    k_ln512<<<MTOT, 256>>>(pQ, lnq_g, lnq_b, 1.f);
    k_gemm_bias<<<dim3(DM/64, MTOT/64), 256>>>(pX, wv_w, wv_b, pV, MTOT, DM, PD);
    k_ln512<<<MTOT, 256>>>(pV, lnv_g, lnv_b, 1.f/(float)NT);
    // 6. M = I + 2VV^T ; X0 = I - 2VV^T ; p = -2 Q V^T + 1/196
    dim3 gNT(4,4,NB);
    k_bgemm<<<gNT,256>>>(pV, pV, pM,  NT, NT, DM, 1,  2.f, 0.f, 1.f);
    k_bgemm<<<gNT,256>>>(pV, pV, pXa, NT, NT, DM, 1, -2.f, 0.f, 1.f);
    k_bgemm<<<gNT,256>>>(pQ, pV, pP,  NT, NT, DM, 1, -2.f, 1.f/(float)NT, 0.f);
    // 7. Newton-Schulz x3: T = 2I - M@X ; X' = X@T
    float* Xc = pXa; float* Xn = pXb;
    for (int i=0;i<3;i++){
        k_bgemm<<<gNT,256>>>(pM, Xc, pT, NT, NT, NT, 0, -1.f, 0.f, 2.f);
        k_bgemm<<<gNT,256>>>(Xc, pT, Xn, NT, NT, NT, 0,  1.f, 0.f, 0.f);
        float* t = Xc; Xc = Xn; Xn = t;
    }
    // 8. ADMM (fused, 50 iters) -> normalized coeffs
    k_admm<<<dim3(4,NB), 343, admm_smem>>>(Xc, pP, pCf);
    // 9. out = coeffs @ V
    k_bgemm<<<dim3(8,4,NB),256>>>(pCf, pV, pO, NT, DM, NT, 0, 1.f, 0.f, 0.f);
    // 10-11. pool + head
    k_pool<<<NB, 256>>>(pO, pPool);
    k_head<<<NB, 256>>>(pPool, mlg, mlb, mlw, mlwb, out);
}

// round 4
// speedup vs baseline: 1.2471x; 1.2471x over previous
#include <cuda_runtime.h>

#define NB 32
#define NT 196
#define PD 768
#define DM 512
#define NC 1000
#define MTOT (NB*NT)

__device__ float g_X [(size_t)MTOT*PD];
__device__ float g_Q [(size_t)MTOT*DM];
__device__ float g_V [(size_t)MTOT*DM];
__device__ float g_M [(size_t)NB*NT*NT];
__device__ float g_Xa[(size_t)NB*NT*NT];
__device__ float g_Xb[(size_t)NB*NT*NT];
__device__ float g_T [(size_t)NB*NT*NT];
__device__ float g_P [(size_t)NB*NT*NT];
__device__ float g_Cf[(size_t)NB*NT*NT];
__device__ float g_O [(size_t)MTOT*DM];
__device__ float g_pool[NB*DM];

__device__ __forceinline__ float clipf(float x){ return fminf(fmaxf(x, 0.f), 1.f); }

__device__ __forceinline__ float4 ld4g(const float* p, int rem){
    if (rem >= 4) return *(const float4*)p;
    float4 v = make_float4(0.f,0.f,0.f,0.f);
    if (rem > 0) v.x = p[0];
    if (rem > 1) v.y = p[1];
    if (rem > 2) v.z = p[2];
    return v;
}

// ---------------- patchify + LN(768) + pos ----------------
__global__ void k_patchify(const float* __restrict__ img, const float* __restrict__ g,
                           const float* __restrict__ bb, const float* __restrict__ pos){
    int bn = blockIdx.x, b = bn / NT, n = bn % NT;
    int hh = n / 14, ww = n % 14;
    int tid = threadIdx.x, ph = tid >> 4, pw = tid & 15;
    const float* ib = img + (size_t)b*3*224*224 + (size_t)(hh*16+ph)*224 + (ww*16+pw);
    float v0 = ib[0], v1 = ib[224*224], v2 = ib[2*224*224];
    __shared__ float red[256]; __shared__ float smu, srs;
    red[tid] = v0+v1+v2; __syncthreads();
    for (int o=128;o;o>>=1){ if (tid<o) red[tid]+=red[tid+o]; __syncthreads(); }
    if (!tid) smu = red[0]/768.f;
    __syncthreads();
    float mu = smu, d0=v0-mu, d1=v1-mu, d2=v2-mu;
    red[tid] = d0*d0+d1*d1+d2*d2; __syncthreads();
    for (int o=128;o;o>>=1){ if (tid<o) red[tid]+=red[tid+o]; __syncthreads(); }
    if (!tid) srs = rsqrtf(red[0]/768.f + 1e-5f);
    __syncthreads();
    float rs = srs;
    float* xo = g_X + (size_t)bn*PD;
    const float* pp = pos + (size_t)n*PD;
    int q = tid;     xo[q] = d0*rs*g[q] + bb[q] + pp[q];
    q = 256+tid;     xo[q] = d1*rs*g[q] + bb[q] + pp[q];
    q = 512+tid;     xo[q] = d2*rs*g[q] + bb[q] + pp[q];
}

// ---------------- fused projections: z=0 -> Q, z=1 -> V. 128x128 tiles, double-buffered ----------------
__global__ void __launch_bounds__(256,2) k_proj(const float* __restrict__ X,
                       const float* __restrict__ Wq, const float* __restrict__ bq,
                       const float* __restrict__ Wv, const float* __restrict__ bv,
                       float* __restrict__ Qo, float* __restrict__ Vo){
    __shared__ float As[2][16][128];
    __shared__ float Bs[2][16][128];
    const float* B   = blockIdx.z ? Wv : Wq;
    const float* bia = blockIdx.z ? bv : bq;
    float* C         = blockIdx.z ? Vo : Qo;
    const int Mv = MTOT, Nv = DM, Kv = PD;
    int tid = threadIdx.x;
    int m0 = blockIdx.y<<7, n0 = blockIdx.x<<7;
    int ty = tid>>4, tx = tid&15;
    int aRow = tid>>1, aK = (tid&1)<<3;
    int bK = tid>>4, bN = (tid&15)<<3;
    const float* Ap = X + (size_t)(m0+aRow)*Kv + aK;
    const float* Bp = B + (size_t)bK*Nv + n0 + bN;
    float4 pa0 = *(const float4*)(Ap);
    float4 pa1 = *(const float4*)(Ap+4);
    float4 pb0 = *(const float4*)(Bp);
    float4 pb1 = *(const float4*)(Bp+4);
    As[0][aK+0][aRow]=pa0.x; As[0][aK+1][aRow]=pa0.y; As[0][aK+2][aRow]=pa0.z; As[0][aK+3][aRow]=pa0.w;
    As[0][aK+4][aRow]=pa1.x; As[0][aK+5][aRow]=pa1.y; As[0][aK+6][aRow]=pa1.z; As[0][aK+7][aRow]=pa1.w;
    *(float4*)&Bs[0][bK][bN] = pb0; *(float4*)&Bs[0][bK][bN+4] = pb1;
    __syncthreads();
    float acc[8][8] = {};
    const int NP = Kv>>4;
    int buf = 0;
    for (int p=0;p<NP;p++){
        bool more = (p+1)<NP;
        if (more){
            int k0 = (p+1)<<4;
            pa0 = *(const float4*)(Ap + k0);
            pa1 = *(const float4*)(Ap + k0 + 4);
            pb0 = *(const float4*)(Bp + (size_t)k0*Nv);
            pb1 = *(const float4*)(Bp + (size_t)k0*Nv + 4);
        }
#pragma unroll
        for (int kk=0;kk<16;kk++){
            float4 a0=*(const float4*)&As[buf][kk][ty<<3];
            float4 a1=*(const float4*)&As[buf][kk][(ty<<3)+4];
            float4 b0=*(const float4*)&Bs[buf][kk][tx<<3];
            float4 b1=*(const float4*)&Bs[buf][kk][(tx<<3)+4];
            float av[8]={a0.x,a0.y,a0.z,a0.w,a1.x,a1.y,a1.z,a1.w};
            float bw[8]={b0.x,b0.y,b0.z,b0.w,b1.x,b1.y,b1.z,b1.w};
#pragma unroll
            for (int r=0;r<8;r++)
#pragma unroll
                for (int c=0;c<8;c++)
                    acc[r][c] = fmaf(av[r], bw[c], acc[r][c]);
        }
        if (more){
            int nb = buf^1;
            As[nb][aK+0][aRow]=pa0.x; As[nb][aK+1][aRow]=pa0.y; As[nb][aK+2][aRow]=pa0.z; As[nb][aK+3][aRow]=pa0.w;
            As[nb][aK+4][aRow]=pa1.x; As[nb][aK+5][aRow]=pa1.y; As[nb][aK+6][aRow]=pa1.z; As[nb][aK+7][aRow]=pa1.w;
            *(float4*)&Bs[nb][bK][bN] = pb0; *(float4*)&Bs[nb][bK][bN+4] = pb1;
            __syncthreads();
            buf = nb;
        }
    }
    float4 bi0 = *(const float4*)(bia + n0 + (tx<<3));
    float4 bi1 = *(const float4*)(bia + n0 + (tx<<3) + 4);
#pragma unroll
    for (int r=0;r<8;r++){
        int gm = m0 + (ty<<3) + r;
        float4 o0 = make_float4(acc[r][0]+bi0.x, acc[r][1]+bi0.y, acc[r][2]+bi0.z, acc[r][3]+bi0.w);
        float4 o1 = make_float4(acc[r][4]+bi1.x, acc[r][5]+bi1.y, acc[r][6]+bi1.z, acc[r][7]+bi1.w);
        *(float4*)(C + (size_t)gm*Nv + n0 + (tx<<3)) = o0;
        *(float4*)(C + (size_t)gm*Nv + n0 + (tx<<3) + 4) = o1;
    }
}

// ---------------- in-place rowwise LN(512), then *scale ----------------
__global__ void k_ln512(float* __restrict__ y0, const float* __restrict__ g,
                        const float* __restrict__ bb, float scale){
    float* y = y0 + (size_t)blockIdx.x*DM;
    int tid = threadIdx.x;
    float v0 = y[tid], v1 = y[tid+256];
    __shared__ float red[256]; __shared__ float smu, srs;
    red[tid] = v0+v1; __syncthreads();
    for (int o=128;o;o>>=1){ if (tid<o) red[tid]+=red[tid+o]; __syncthreads(); }
    if (!tid) smu = red[0]/512.f;
    __syncthreads();
    float mu = smu, d0=v0-mu, d1=v1-mu;
    red[tid] = d0*d0+d1*d1; __syncthreads();
    for (int o=128;o;o>>=1){ if (tid<o) red[tid]+=red[tid+o]; __syncthreads(); }
    if (!tid) srs = rsqrtf(red[0]/512.f + 1e-5f);
    __syncthreads();
    float rs = srs;
    y[tid]     = (d0*rs*g[tid]     + bb[tid])     * scale;
    y[tid+256] = (d1*rs*g[tid+256] + bb[tid+256]) * scale;
}

// ---------------- batched GEMM 128x128 tiles, double-buffered, guards ----------------
// C = alpha*A@op(B) + c0 + diag*I
__global__ void __launch_bounds__(256,2) k_bgemm(const float* __restrict__ A0, const float* __restrict__ B0,
                        float* __restrict__ C0, int M, int N, int K, int transB,
                        float alpha, float c0, float diag){
    __shared__ float As[2][16][128];
    __shared__ float Bs[2][16][128];
    const float* A = A0 + (size_t)blockIdx.z*M*K;
    const float* B = B0 + (size_t)blockIdx.z*((size_t)N*K);
    float* C = C0 + (size_t)blockIdx.z*M*N;
    int tid = threadIdx.x;
    int m0 = blockIdx.y<<7, n0 = blockIdx.x<<7;
    int ty = tid>>4, tx = tid&15;
    int aRow = tid>>1, aK = (tid&1)<<3;
    bool aok = (m0+aRow) < M;
    int bRT = tid>>1, bKT = (tid&1)<<3;   // transB scatter mapping
    bool bokT = (n0+bRT) < N;
    int bK = tid>>4, bN = (tid&15)<<3;    // NN mapping
    const int NP = (K+15)>>4;
    float4 pa0,pa1,pb0,pb1;
    {
        const float* Ap = A + (size_t)(m0+aRow)*K + aK;
        int remA = aok ? (K - aK) : 0;
        pa0 = ld4g(Ap, remA); pa1 = ld4g(Ap+4, remA-4);
        if (transB){
            const float* Bp = B + (size_t)(n0+bRT)*K + bKT;
            int remB = bokT ? (K - bKT) : 0;
            pb0 = ld4g(Bp, remB); pb1 = ld4g(Bp+4, remB-4);
        } else {
            const float* Bp = B + (size_t)bK*N + n0 + bN;
            int remB = (bK < K) ? (N-(n0+bN)) : 0;
            pb0 = ld4g(Bp, remB); pb1 = ld4g(Bp+4, remB-4);
        }
    }
    As[0][aK+0][aRow]=pa0.x; As[0][aK+1][aRow]=pa0.y; As[0][aK+2][aRow]=pa0.z; As[0][aK+3][aRow]=pa0.w;
    As[0][aK+4][aRow]=pa1.x; As[0][aK+5][aRow]=pa1.y; As[0][aK+6][aRow]=pa1.z; As[0][aK+7][aRow]=pa1.w;
    if (transB){
        Bs[0][bKT+0][bRT]=pb0.x; Bs[0][bKT+1][bRT]=pb0.y; Bs[0][bKT+2][bRT]=pb0.z; Bs[0][bKT+3][bRT]=pb0.w;
        Bs[0][bKT+4][bRT]=pb1.x; Bs[0][bKT+5][bRT]=pb1.y; Bs[0][bKT+6][bRT]=pb1.z; Bs[0][bKT+7][bRT]=pb1.w;
    } else {
        *(float4*)&Bs[0][bK][bN] = pb0; *(float4*)&Bs[0][bK][bN+4] = pb1;
    }
    __syncthreads();
    float acc[8][8] = {};
    int buf = 0;
    for (int p=0;p<NP;p++){
        bool more = (p+1)<NP;
        if (more){
            int k0 = (p+1)<<4;
            const float* Ap = A + (size_t)(m0+aRow)*K + k0 + aK;
            int remA = aok ? (K - (k0+aK)) : 0;
            pa0 = ld4g(Ap, remA); pa1 = ld4g(Ap+4, remA-4);
            if (transB){
                const float* Bp = B + (size_t)(n0+bRT)*K + k0 + bKT;
                int remB = bokT ? (K - (k0+bKT)) : 0;
                pb0 = ld4g(Bp, remB); pb1 = ld4g(Bp+4, remB-4);
            } else {
                const float* Bp = B + (size_t)(k0+bK)*N + n0 + bN;
                int remB = ((k0+bK) < K) ? (N-(n0+bN)) : 0;
                pb0 = ld4g(Bp, remB); pb1 = ld4g(Bp+4, remB-4);
            }
        }
#pragma unroll
        for (int kk=0;kk<16;kk++){
            float4 a0=*(const float4*)&As[buf][kk][ty<<3];
            float4 a1=*(const float4*)&As[buf][kk][(ty<<3)+4];
            float4 b0=*(const float4*)&Bs[buf][kk][tx<<3];
            float4 b1=*(const float4*)&Bs[buf][kk][(tx<<3)+4];
            float av[8]={a0.x,a0.y,a0.z,a0.w,a1.x,a1.y,a1.z,a1.w};
            float bw[8]={b0.x,b0.y,b0.z,b0.w,b1.x,b1.y,b1.z,b1.w};
#pragma unroll
            for (int r=0;r<8;r++)
#pragma unroll
                for (int c=0;c<8;c++)
                    acc[r][c] = fmaf(av[r], bw[c], acc[r][c]);
        }
        if (more){
            int nb = buf^1;
            As[nb][aK+0][aRow]=pa0.x; As[nb][aK+1][aRow]=pa0.y; As[nb][aK+2][aRow]=pa0.z; As[nb][aK+3][aRow]=pa0.w;
            As[nb][aK+4][aRow]=pa1.x; As[nb][aK+5][aRow]=pa1.y; As[nb][aK+6][aRow]=pa1.z; As[nb][aK+7][aRow]=pa1.w;
            if (transB){
                Bs[nb][bKT+0][bRT]=pb0.x; Bs[nb][bKT+1][bRT]=pb0.y; Bs[nb][bKT+2][bRT]=pb0.z; Bs[nb][bKT+3][bRT]=pb0.w;
                Bs[nb][bKT+4][bRT]=pb1.x; Bs[nb][bKT+5][bRT]=pb1.y; Bs[nb][bKT+6][bRT]=pb1.z; Bs[nb][bKT+7][bRT]=pb1.w;
            } else {
                *(float4*)&Bs[nb][bK][bN] = pb0; *(float4*)&Bs[nb][bK][bN+4] = pb1;
            }
            __syncthreads();
            buf = nb;
        }
    }
#pragma unroll
    for (int r=0;r<8;r++){
        int gm = m0 + (ty<<3) + r;
        if (gm >= M) continue;
#pragma unroll
        for (int c=0;c<8;c++){
            int gn = n0 + (tx<<3) + c;
            if (gn >= N) continue;
            C[(size_t)gm*N+gn] = fmaf(alpha, acc[r][c], c0) + ((gm==gn)?diag:0.f);
        }
    }
}

// ---------------- X0 = 2I - M (elementwise) ----------------
__global__ void k_x0(const float* __restrict__ Mm, float* __restrict__ X){
    size_t idx = (size_t)blockIdx.x*256 + threadIdx.x;
    if (idx >= (size_t)NB*NT*NT) return;
    int w = (int)(idx % (NT*NT));
    int i = w / NT, j = w - i*NT;
    X[idx] = ((i==j)?2.f:0.f) - Mm[idx];
}

// ---------------- fused ADMM: 50 iters, conflict-free smem layout ----------------
// grid (4 token-blocks, 32 batches), 343 threads. ii=tid/7 owns rows {ii,ii+49,ii+98,ii+147},
// nn=tid%7 owns tokens nn*7..+6. Row stride 204 floats => stride mod 32 = 12, gcd 4 =>
// 5 consecutive ii rows land on distinct bank groups; interleaved rows keep ii-stride = 1 row.
#define SMSTR 204
__global__ void k_admm(const float* __restrict__ Minv, const float* __restrict__ P,
                       float* __restrict__ Cf){
    extern __shared__ float sm[];
    float* sM = sm;                   // 196 x SMSTR
    float* sR = sm + NT*SMSTR;        // 49 x SMSTR
    int b = blockIdx.y, tb = blockIdx.x;
    int tid = threadIdx.x;
    int ii = tid/7, nn = tid - ii*7;
    const float* Mb = Minv + (size_t)b*NT*NT;
    for (int idx = tid; idx < NT*NT; idx += 343){
        int r = idx/NT, c = idx - r*NT;
        sM[r*SMSTR + c] = Mb[idx];
    }
    float p[7][4], s[7][4];
    const float* Pb = P + ((size_t)b*NT + tb*49)*NT;
#pragma unroll
    for (int t=0;t<7;t++)
#pragma unroll
        for (int r=0;r<4;r++)
            p[t][r] = Pb[(size_t)(nn*7+t)*NT + ii + 49*r];
    __syncthreads();
    const float* m0p = sM + (size_t)ii*SMSTR;
    const float* m1p = sM + (size_t)(ii+49)*SMSTR;
    const float* m2p = sM + (size_t)(ii+98)*SMSTR;
    const float* m3p = sM + (size_t)(ii+147)*SMSTR;
    for (int it=0; it<50; it++){
#pragma unroll
        for (int t=0;t<7;t++){
            int base = (nn*7+t)*SMSTR + ii;
#pragma unroll
            for (int r=0;r<4;r++){
                float rv;
                if (it==0) rv = -p[t][r];
                else { float sv = s[t][r]; rv = 2.f*clipf(sv) - sv - p[t][r]; }
                sR[base + 49*r] = rv;
            }
        }
        __syncthreads();
        float acc[7][4] = {};
        for (int j=0;j<NT;j+=4){
            float4 m0 = *(const float4*)(m0p+j);
            float4 m1 = *(const float4*)(m1p+j);
            float4 m2 = *(const float4*)(m2p+j);
            float4 m3 = *(const float4*)(m3p+j);
#pragma unroll
            for (int t=0;t<7;t++){
                float4 rv = *(const float4*)(sR + (nn*7+t)*SMSTR + j);
                acc[t][0]=fmaf(m0.x,rv.x,fmaf(m0.y,rv.y,fmaf(m0.z,rv.z,fmaf(m0.w,rv.w,acc[t][0]))));
                acc[t][1]=fmaf(m1.x,rv.x,fmaf(m1.y,rv.y,fmaf(m1.z,rv.z,fmaf(m1.w,rv.w,acc[t][1]))));
                acc[t][2]=fmaf(m2.x,rv.x,fmaf(m2.y,rv.y,fmaf(m2.z,rv.z,fmaf(m2.w,rv.w,acc[t][2]))));
                acc[t][3]=fmaf(m3.x,rv.x,fmaf(m3.y,rv.y,fmaf(m3.z,rv.z,fmaf(m3.w,rv.w,acc[t][3]))));
            }
        }
#pragma unroll
        for (int t=0;t<7;t++)
#pragma unroll
            for (int r=0;r<4;r++)
                s[t][r] = (it==0) ? acc[t][r] : acc[t][r] + s[t][r] - clipf(s[t][r]);
        __syncthreads();
    }
    // z = clip(s) -> sR, then rowwise normalize and write coeffs
#pragma unroll
    for (int t=0;t<7;t++){
        int base = (nn*7+t)*SMSTR + ii;
#pragma unroll
        for (int r=0;r<4;r++)
            sR[base + 49*r] = clipf(s[t][r]);
    }
    __syncthreads();
    if (tid < 49){
        float sum = 0.f;
        for (int j=0;j<NT;j++) sum += sR[tid*SMSTR+j];
        sM[tid] = 1.f/(sum + 1e-10f);
    }
    __syncthreads();
    float* Cb = Cf + ((size_t)b*NT + tb*49)*NT;
#pragma unroll
    for (int t=0;t<7;t++){
        int tk = nn*7+t;
        float inv = sM[tk];
#pragma unroll
        for (int r=0;r<4;r++)
            Cb[(size_t)tk*NT + ii + 49*r] = sR[tk*SMSTR + ii + 49*r]*inv;
    }
}

// ---------------- pool: mean over tokens ----------------
__global__ void k_pool(const float* __restrict__ O, float* __restrict__ pooled){
    int b = blockIdx.x, tid = threadIdx.x;
    const float* Ob = O + (size_t)b*NT*DM;
    float s0=0.f, s1=0.f;
    for (int n=0;n<NT;n++){ s0 += Ob[(size_t)n*DM+tid]; s1 += Ob[(size_t)n*DM+256+tid]; }
    pooled[b*DM+tid] = s0/(float)NT;
    pooled[b*DM+256+tid] = s1/(float)NT;
}

// ---------------- head: LN + GEMM(512x1000) + softmax ----------------
__global__ void k_head(const float* __restrict__ pooled, const float* __restrict__ g,
                       const float* __restrict__ bb, const float* __restrict__ W,
                       const float* __restrict__ wb, float* __restrict__ out){
    int b = blockIdx.x, tid = threadIdx.x;
    __shared__ float xs[512]; __shared__ float red[256]; __shared__ float smu, srs, sred;
    float v0 = pooled[b*DM+tid], v1 = pooled[b*DM+256+tid];
    red[tid] = v0+v1; __syncthreads();
    for (int o=128;o;o>>=1){ if (tid<o) red[tid]+=red[tid+o]; __syncthreads(); }
    if (!tid) smu = red[0]/512.f;
    __syncthreads();
    float mu = smu, d0=v0-mu, d1=v1-mu;
    red[tid] = d0*d0+d1*d1; __syncthreads();
    for (int o=128;o;o>>=1){ if (tid<o) red[tid]+=red[tid+o]; __syncthreads(); }
    if (!tid) srs = rsqrtf(red[0]/512.f + 1e-5f);
    __syncthreads();
    float rs = srs;
    xs[tid] = d0*rs*g[tid]+bb[tid];
    xs[tid+256] = d1*rs*g[tid+256]+bb[tid+256];
    __syncthreads();
    float lg[4];
#pragma unroll
    for (int c4=0;c4<4;c4++){
        int c = c4*256 + tid;
        float acc = 0.f;
        if (c < NC){
            for (int k=0;k<512;k++) acc = fmaf(xs[k], W[(size_t)k*NC+c], acc);
            acc += wb[c];
        } else acc = -1e30f;
        lg[c4] = acc;
    }
    float mx = fmaxf(fmaxf(lg[0],lg[1]),fmaxf(lg[2],lg[3]));
    red[tid] = mx; __syncthreads();
    for (int o=128;o;o>>=1){ if (tid<o) red[tid]=fmaxf(red[tid],red[tid+o]); __syncthreads(); }
    if (!tid) sred = red[0];
    __syncthreads();
    mx = sred;
    float es = 0.f;
#pragma unroll
    for (int c4=0;c4<4;c4++){ lg[c4] = __expf(lg[c4]-mx); if (c4*256+tid < NC) es += lg[c4]; }
    red[tid] = es; __syncthreads();
    for (int o=128;o;o>>=1){ if (tid<o) red[tid]+=red[tid+o]; __syncthreads(); }
    if (!tid) sred = red[0];
    __syncthreads();
    float inv = 1.f/sred;
#pragma unroll
    for (int c4=0;c4<4;c4++){ int c = c4*256+tid; if (c < NC) out[(size_t)b*NC+c] = lg[c4]*inv; }
}

extern "C" void kernel_launch(void* const* d_in, const int* in_sizes, int n_in,
                              void* d_out, int out_size){
    const float* img   = (const float*)d_in[0];
    const float* lpg   = (const float*)d_in[1];
    const float* lpb   = (const float*)d_in[2];
    const float* wq_w  = (const float*)d_in[3];
    const float* wq_b  = (const float*)d_in[4];
    const float* lnq_g = (const float*)d_in[5];
    const float* lnq_b = (const float*)d_in[6];
    const float* wv_w  = (const float*)d_in[7];
    const float* wv_b  = (const float*)d_in[8];
    const float* lnv_g = (const float*)d_in[9];
    const float* lnv_b = (const float*)d_in[10];
    const float* pos   = (const float*)d_in[11];
    const float* mlg   = (const float*)d_in[12];
    const float* mlb   = (const float*)d_in[13];
    const float* mlw   = (const float*)d_in[14];
    const float* mlwb  = (const float*)d_in[15];
    float* out = (float*)d_out;

    float *pX,*pQ,*pV,*pM,*pXa,*pXb,*pT,*pP,*pCf,*pO,*pPool;
    cudaGetSymbolAddress((void**)&pX, g_X);
    cudaGetSymbolAddress((void**)&pQ, g_Q);
    cudaGetSymbolAddress((void**)&pV, g_V);
    cudaGetSymbolAddress((void**)&pM, g_M);
    cudaGetSymbolAddress((void**)&pXa, g_Xa);
    cudaGetSymbolAddress((void**)&pXb, g_Xb);
    cudaGetSymbolAddress((void**)&pT, g_T);
    cudaGetSymbolAddress((void**)&pP, g_P);
    cudaGetSymbolAddress((void**)&pCf, g_Cf);
    cudaGetSymbolAddress((void**)&pO, g_O);
    cudaGetSymbolAddress((void**)&pPool, g_pool);

    const int admm_smem = (NT*SMSTR + 49*SMSTR)*4;
    static int s_attr_done = 0;
    if (!s_attr_done){
        cudaFuncSetAttribute(k_admm, cudaFuncAttributeMaxDynamicSharedMemorySize, admm_smem);
        s_attr_done = 1;
    }

    // 1. patchify + LN + pos
    k_patchify<<<MTOT, 256>>>(img, lpg, lpb, pos);
    // 2. fused Q/V projections + LN (V scaled by 1/196)
    k_proj<<<dim3(DM/128, MTOT/128, 2), 256>>>(pX, wq_w, wq_b, wv_w, wv_b, pQ, pV);
    k_ln512<<<MTOT, 256>>>(pQ, lnq_g, lnq_b, 1.f);
    k_ln512<<<MTOT, 256>>>(pV, lnv_g, lnv_b, 1.f/(float)NT);
    // 3. M = I + 2VV^T ; p = -2 Q V^T + 1/196 ; X0 = 2I - M
    dim3 gNT(2,2,NB);
    k_bgemm<<<gNT,256>>>(pV, pV, pM, NT, NT, DM, 1,  2.f, 0.f, 1.f);
    k_bgemm<<<gNT,256>>>(pQ, pV, pP, NT, NT, DM, 1, -2.f, 1.f/(float)NT, 0.f);
    k_x0<<<(NB*NT*NT + 255)/256, 256>>>(pM, pXa);
    // 4. Newton-Schulz x3: T = 2I - M@X ; X' = X@T
    float* Xc = pXa; float* Xn = pXb;
    for (int i=0;i<3;i++){
        k_bgemm<<<gNT,256>>>(pM, Xc, pT, NT, NT, NT, 0, -1.f, 0.f, 2.f);
        k_bgemm<<<gNT,256>>>(Xc, pT, Xn, NT, NT, NT, 0,  1.f, 0.f, 0.f);
        float* t = Xc; Xc = Xn; Xn = t;
    }
    // 5. ADMM (fused, 50 iters) -> normalized coeffs
    k_admm<<<dim3(4,NB), 343, admm_smem>>>(Xc, pP, pCf);
    // 6. out = coeffs @ V
    k_bgemm<<<dim3(4,2,NB),256>>>(pCf, pV, pO, NT, DM, NT, 0, 1.f, 0.f, 0.f);
    // 7. pool + head
    k_pool<<<NB, 256>>>(pO, pPool);
    k_head<<<NB, 256>>>(pPool, mlg, mlb, mlw, mlwb, out);
}